// round 16
// baseline (speedup 1.0000x reference)
#include <cuda_runtime.h>
#include <cuda_bf16.h>

#define Cdim   128
#define HW     102400          // 320*320
#define APITCH 104             // act/epi/t pitch (elems)
#define SXP    108             // sx pitch (f32 words): conflict-free patch reads

// fragment-order A operands: [tile][ks][lane][4 x u32]
__device__ __align__(16) unsigned g_WmainFrag[8 * 16 * 32 * 4];  // 64KB
__device__ __align__(16) unsigned g_Wdm1Frag[2 * 8 * 32 * 4];    // 8KB
__device__ __align__(16) unsigned g_Wdm2Frag[8 * 2 * 32 * 4];    // 2KB

__device__ __forceinline__ unsigned pack_bf2f(float lo, float hi) {
    unsigned u;
    asm("cvt.rn.bf16x2.f32 %0, %1, %2;" : "=r"(u) : "f"(hi), "f"(lo));
    return u;
}

__global__ void precompute_pack_kernel(const float* __restrict__ w_h_pw,
                                       const float* __restrict__ w_v_pw,
                                       const float* __restrict__ w_dm1,
                                       const float* __restrict__ w_dm2,
                                       const float* __restrict__ w_fuse) {
    __shared__ float wf[256];
    int o = blockIdx.x;
    int tid = threadIdx.x;            // 256
    // PDL: allow the dependent (main) kernel to launch immediately — it only
    // consumes our outputs after its own P2 + cudaGridDependencySynchronize().
    if (tid == 0) cudaTriggerProgrammaticLaunchCompletion();
    if (o < 128) {
        wf[tid] = w_fuse[o * 256 + tid];
        __syncthreads();
        int s = tid >> 7, t = tid & 127;
        const float* mat = s ? w_v_pw : w_h_pw;
        const float* wrow = wf + s * 128;
        float a0 = 0.f, a1 = 0.f, a2 = 0.f, a3 = 0.f;
        #pragma unroll
        for (int j = 0; j < 128; j += 4) {
            a0 += wrow[j    ] * __ldg(mat + (j    ) * 128 + t);
            a1 += wrow[j + 1] * __ldg(mat + (j + 1) * 128 + t);
            a2 += wrow[j + 2] * __ldg(mat + (j + 2) * 128 + t);
            a3 += wrow[j + 3] * __ldg(mat + (j + 3) * 128 + t);
        }
        float acc = (a0 + a1) + (a2 + a3);
        float hi = __shfl_down_sync(0xffffffffu, acc, 1);
        if ((t & 1) == 0) {
            int col = s * 128 + t;
            int rt = o & 15, ot = o >> 4;
            int ks = col >> 4, ct = col & 15;
            int lane_f = (rt & 7) * 4 + ((ct & 7) >> 1);
            int j = (rt >> 3) | ((ct >> 3) << 1);
            g_WmainFrag[((ot * 16 + ks) * 32 + lane_f) * 4 + j] = pack_bf2f(acc, hi);
        }
    } else if (o == 128) {
        for (int idx = tid; idx < 2048; idx += 256) {   // dm1 frags [2][8][32][4]
            int j = idx & 3, lane = (idx >> 2) & 31, ks = (idx >> 7) & 7, mt = idx >> 10;
            int row = mt * 16 + (lane >> 2) + (j & 1) * 8;
            int col = ks * 16 + (lane & 3) * 2 + (j >> 1) * 8;
            g_Wdm1Frag[idx] = pack_bf2f(w_dm1[row * 128 + col], w_dm1[row * 128 + col + 1]);
        }
    } else {
        for (int idx = tid; idx < 512; idx += 256) {    // dm2 frags [8][2][32][4]
            int j = idx & 3, lane = (idx >> 2) & 31, ks = (idx >> 7) & 1, ot = idx >> 8;
            int row = ot * 16 + (lane >> 2) + (j & 1) * 8;
            int col = ks * 16 + (lane & 3) * 2 + (j >> 1) * 8;
            g_Wdm2Frag[idx] = pack_bf2f(w_dm2[row * 32 + col], w_dm2[row * 32 + col + 1]);
        }
    }
}

// ---- mma helpers ----
__device__ __forceinline__ void ldmatrix_x2t(unsigned &r0, unsigned &r1, unsigned addr) {
    asm volatile("ldmatrix.sync.aligned.m8n8.x2.trans.shared.b16 {%0,%1}, [%2];"
                 : "=r"(r0), "=r"(r1) : "r"(addr));
}
__device__ __forceinline__ void ldmatrix_x4t(unsigned &r0, unsigned &r1,
                                             unsigned &r2, unsigned &r3, unsigned addr) {
    asm volatile("ldmatrix.sync.aligned.m8n8.x4.trans.shared.b16 {%0,%1,%2,%3}, [%4];"
                 : "=r"(r0), "=r"(r1), "=r"(r2), "=r"(r3) : "r"(addr));
}
__device__ __forceinline__ void mma_bf16(float &c0, float &c1, float &c2, float &c3,
                                         unsigned a0, unsigned a1, unsigned a2, unsigned a3,
                                         unsigned b0, unsigned b1) {
    asm volatile("mma.sync.aligned.m16n8k16.row.col.f32.bf16.bf16.f32 "
                 "{%0,%1,%2,%3}, {%4,%5,%6,%7}, {%8,%9}, {%0,%1,%2,%3};"
                 : "+f"(c0), "+f"(c1), "+f"(c2), "+f"(c3)
                 : "r"(a0), "r"(a1), "r"(a2), "r"(a3), "r"(b0), "r"(b1));
}

__device__ __forceinline__ float lrelu(float x) { return fmaxf(x, 0.1f * x); }

__device__ __forceinline__ void conv5(const float w[5],
                                      float x0, float x1, float x2, float x3, float x4,
                                      float o[5]) {
    o[0] = w[2]*x0 + w[3]*x1 + w[4]*x2;
    o[1] = w[1]*x0 + w[2]*x1 + w[3]*x2 + w[4]*x3;
    o[2] = w[0]*x0 + w[1]*x1 + w[2]*x2 + w[3]*x3 + w[4]*x4;
    o[3] = w[0]*x1 + w[1]*x2 + w[2]*x3 + w[3]*x4;
    o[4] = w[0]*x2 + w[1]*x3 + w[2]*x4;
}

__device__ __forceinline__ void store5(__nv_bfloat16* p, int sub,
                                       float a0, float a1, float a2, float a3, float a4) {
    a0 = lrelu(a0); a1 = lrelu(a1); a2 = lrelu(a2); a3 = lrelu(a3); a4 = lrelu(a4);
    if (sub & 1) {
        p[0] = __float2bfloat16(a0);
        *(__nv_bfloat162*)(p + 1) = __floats2bfloat162_rn(a1, a2);
        *(__nv_bfloat162*)(p + 3) = __floats2bfloat162_rn(a3, a4);
    } else {
        *(__nv_bfloat162*)(p)     = __floats2bfloat162_rn(a0, a1);
        *(__nv_bfloat162*)(p + 2) = __floats2bfloat162_rn(a2, a3);
        p[4] = __float2bfloat16(a4);
    }
}

// ---- shared memory layout (bytes) ----
// 0      : act [256][APITCH] bf16  53248   (d_s aliases after P3)
// 53248  : region (55296):
//            sx    f32 [128][SXP]      55296  (P1/P2 only)
//            epi_s [128][APITCH] bf16  26624  (+0)
//            t_s   [32][APITCH]  bf16   6656  (+26624)
// total 108544  -> 2 CTAs/SM
#define SMEM_BYTES 108544

__global__ __launch_bounds__(512, 2)
void epi_mma_kernel(const float* __restrict__ x,
                    const float* __restrict__ w_h_dw,
                    const float* __restrict__ w_v_dw,
                    const float* __restrict__ scale_p,
                    float* __restrict__ out) {
    extern __shared__ char smem[];
    __nv_bfloat16* act   = (__nv_bfloat16*)(smem);
    char* region = smem + 53248;
    float* sx            = (float*)(region);
    __nv_bfloat16* epi_s = (__nv_bfloat16*)(region);
    __nv_bfloat16* t_s   = (__nv_bfloat16*)(region + 26624);
    __nv_bfloat16* d_s = act;   // alias; act dead after P3

    const int tid  = threadIdx.x;
    const int lane = tid & 31;
    const int warp = tid >> 5;
    const int C0 = blockIdx.x * 20;
    const int R0 = blockIdx.y * 5;
    const int b  = blockIdx.z;
    const float* xb = x + (long)b * Cdim * HW;

    // ---- P1: stage x tile (coalesced float4): 6 full rounds + 128-thread tail ----
    #pragma unroll
    for (int it = 0; it < 6; ++it) {
        int idx = tid + it * 512;
        int row = idx / 5, q = idx - row * 5;
        int c = row / 5, r = row - c * 5;
        float4 v = *(const float4*)(xb + (long)c * HW + (R0 + r) * 320 + C0 + q * 4);
        *(float4*)(sx + c * SXP + r * 20 + q * 4) = v;
    }
    if (tid < 128) {
        int idx = tid + 3072;
        int row = idx / 5, q = idx - row * 5;
        int c = row / 5, r = row - c * 5;
        float4 v = *(const float4*)(xb + (long)c * HW + (R0 + r) * 320 + C0 + q * 4);
        *(float4*)(sx + c * SXP + r * 20 + q * 4) = v;
    }
    {   // zero act cols 100..103 for all 256 rows
        int k = tid >> 1, q = tid & 1;
        *(__nv_bfloat162*)(act + k * APITCH + 100 + q * 2) = __floats2bfloat162_rn(0.f, 0.f);
    }
    __syncthreads();

    // ---- P2: depthwise 1x5 / 5x1 on one 5x5 patch + lrelu -> act bf16 [K][N] ----
    {
        const int c = tid >> 2, sub = tid & 3;
        float wh[5], wv[5];
        #pragma unroll
        for (int k = 0; k < 5; ++k) {
            wh[k] = __ldg(w_h_dw + c * 5 + k);
            wv[k] = __ldg(w_v_dw + c * 5 + k);
        }
        const float* sp = sx + c * SXP + sub * 5;
        __nv_bfloat16* ah = act + c * APITCH + sub * 5;
        __nv_bfloat16* av = act + (128 + c) * APITCH + sub * 5;

        float va[5][5];
        #pragma unroll
        for (int ro = 0; ro < 5; ++ro)
            #pragma unroll
            for (int j = 0; j < 5; ++j) va[ro][j] = 0.f;

        #pragma unroll
        for (int rr = 0; rr < 5; ++rr) {
            float xr[5];
            #pragma unroll
            for (int j = 0; j < 5; ++j) xr[j] = sp[rr * 20 + j];
            float o[5];
            conv5(wh, xr[0], xr[1], xr[2], xr[3], xr[4], o);
            store5(ah + rr * 20, sub, o[0], o[1], o[2], o[3], o[4]);
            #pragma unroll
            for (int k = 0; k < 5; ++k) {
                int ro = rr + 2 - k;
                if (ro >= 0 && ro < 5) {
                    float w = wv[k];
                    #pragma unroll
                    for (int j = 0; j < 5; ++j) va[ro][j] += w * xr[j];
                }
            }
        }
        #pragma unroll
        for (int ro = 0; ro < 5; ++ro)
            store5(av + ro * 20, sub, va[ro][0], va[ro][1], va[ro][2], va[ro][3], va[ro][4]);
    }
    // PDL: weights produced by the prologue are consumed from here on.
    cudaGridDependencySynchronize();
    __syncthreads();   // act ready; sx dead

    // ---- P3: main GEMM epi[128][104] = Wm[128][256] @ act[256][104] ----
    const int mg   = warp & 3;
    const int ng   = warp >> 2;
    const int nt0  = (ng == 0) ? 0 : 4 + (ng - 1) * 3;
    const int ncnt = (ng == 0) ? 4 : 3;
    const int r  = lane >> 2, cp = (lane & 3) * 2;

    {
        float acc[2][4][4];
        #pragma unroll
        for (int mi = 0; mi < 2; ++mi)
            #pragma unroll
            for (int j = 0; j < 4; ++j)
                acc[mi][j][0] = acc[mi][j][1] = acc[mi][j][2] = acc[mi][j][3] = 0.f;

        const uint4* fA0 = ((const uint4*)g_WmainFrag) + (2 * mg) * 16 * 32 + lane;
        const uint4* fA1 = fA0 + 16 * 32;
        unsigned bBase = (unsigned)__cvta_generic_to_shared(act)
                         + ((lane & 15) * APITCH + (nt0 + (lane >> 4)) * 8) * 2;
        uint4 a0 = fA0[0];
        uint4 a1 = fA1[0];
        #pragma unroll
        for (int ks = 0; ks < 16; ++ks) {
            // prefetch next A fragments (L2-latency hiding; L1 is smem-squeezed)
            int nk = (ks < 15) ? (ks + 1) : 15;
            uint4 na0 = fA0[nk * 32];
            uint4 na1 = fA1[nk * 32];
            unsigned bRow = bBase + ks * 16 * APITCH * 2;
            unsigned b0, b1, b2, b3;
            ldmatrix_x4t(b0, b1, b2, b3, bRow);               // tiles nt0, nt0+1
            mma_bf16(acc[0][0][0], acc[0][0][1], acc[0][0][2], acc[0][0][3],
                     a0.x, a0.y, a0.z, a0.w, b0, b1);
            mma_bf16(acc[1][0][0], acc[1][0][1], acc[1][0][2], acc[1][0][3],
                     a1.x, a1.y, a1.z, a1.w, b0, b1);
            mma_bf16(acc[0][1][0], acc[0][1][1], acc[0][1][2], acc[0][1][3],
                     a0.x, a0.y, a0.z, a0.w, b2, b3);
            mma_bf16(acc[1][1][0], acc[1][1][1], acc[1][1][2], acc[1][1][3],
                     a1.x, a1.y, a1.z, a1.w, b2, b3);
            if (ncnt == 4) {
                ldmatrix_x4t(b0, b1, b2, b3, bRow + 32);      // tiles nt0+2, nt0+3
                mma_bf16(acc[0][2][0], acc[0][2][1], acc[0][2][2], acc[0][2][3],
                         a0.x, a0.y, a0.z, a0.w, b0, b1);
                mma_bf16(acc[1][2][0], acc[1][2][1], acc[1][2][2], acc[1][2][3],
                         a1.x, a1.y, a1.z, a1.w, b0, b1);
                mma_bf16(acc[0][3][0], acc[0][3][1], acc[0][3][2], acc[0][3][3],
                         a0.x, a0.y, a0.z, a0.w, b2, b3);
                mma_bf16(acc[1][3][0], acc[1][3][1], acc[1][3][2], acc[1][3][3],
                         a1.x, a1.y, a1.z, a1.w, b2, b3);
            } else {
                ldmatrix_x2t(b0, b1, bRow + 32);              // tile nt0+2 (lanes 0-15)
                mma_bf16(acc[0][2][0], acc[0][2][1], acc[0][2][2], acc[0][2][3],
                         a0.x, a0.y, a0.z, a0.w, b0, b1);
                mma_bf16(acc[1][2][0], acc[1][2][1], acc[1][2][2], acc[1][2][3],
                         a1.x, a1.y, a1.z, a1.w, b0, b1);
            }
            a0 = na0;
            a1 = na1;
        }
        #pragma unroll
        for (int mi = 0; mi < 2; ++mi) {
            int o0 = (2 * mg + mi) * 16;
            #pragma unroll
            for (int j = 0; j < 4; ++j) {
                if (j < ncnt) {
                    int n = (nt0 + j) * 8 + cp;
                    *(__nv_bfloat162*)(epi_s + (o0 + r) * APITCH + n)
                        = __floats2bfloat162_rn(acc[mi][j][0], acc[mi][j][1]);
                    *(__nv_bfloat162*)(epi_s + (o0 + r + 8) * APITCH + n)
                        = __floats2bfloat162_rn(acc[mi][j][2], acc[mi][j][3]);
                }
            }
        }
    }
    __syncthreads();   // epi ready (sx region now epi)

    // ---- P4: dm1 t[32][104] = lrelu(Wdm1[32][128] @ epi) ----
    {
        int mt = warp & 1, m0 = mt * 16;
        int nt1 = warp >> 1;
        int nt2 = nt1 + 8;
        bool has2 = (warp < 10);
        float c1[4] = {0.f, 0.f, 0.f, 0.f}, c2[4] = {0.f, 0.f, 0.f, 0.f};
        const uint4* wf1 = ((const uint4*)g_Wdm1Frag) + mt * 8 * 32 + lane;
        unsigned bB = (unsigned)__cvta_generic_to_shared(epi_s)
                      + ((lane & 15) * APITCH) * 2;
        if (has2) {
            unsigned bB4 = bB + ((nt1 + (lane >> 4) * 8) * 8) * 2;
            uint4 a = wf1[0];
            #pragma unroll
            for (int ks = 0; ks < 8; ++ks) {
                int nk = (ks < 7) ? (ks + 1) : 7;
                uint4 na = wf1[nk * 32];
                unsigned b0, b1, b2, b3;
                ldmatrix_x4t(b0, b1, b2, b3, bB4 + ks * 16 * APITCH * 2);
                mma_bf16(c1[0], c1[1], c1[2], c1[3], a.x, a.y, a.z, a.w, b0, b1);
                mma_bf16(c2[0], c2[1], c2[2], c2[3], a.x, a.y, a.z, a.w, b2, b3);
                a = na;
            }
        } else {
            #pragma unroll
            for (int ks = 0; ks < 8; ++ks) {
                uint4 a = wf1[ks * 32];
                unsigned b0, b1;
                ldmatrix_x2t(b0, b1, bB + ks * 16 * APITCH * 2 + nt1 * 16);
                mma_bf16(c1[0], c1[1], c1[2], c1[3], a.x, a.y, a.z, a.w, b0, b1);
            }
        }
        {
            int n = nt1 * 8 + cp;
            *(__nv_bfloat162*)(t_s + (m0 + r) * APITCH + n)
                = __floats2bfloat162_rn(lrelu(c1[0]), lrelu(c1[1]));
            *(__nv_bfloat162*)(t_s + (m0 + r + 8) * APITCH + n)
                = __floats2bfloat162_rn(lrelu(c1[2]), lrelu(c1[3]));
        }
        if (has2) {
            int n = nt2 * 8 + cp;
            *(__nv_bfloat162*)(t_s + (m0 + r) * APITCH + n)
                = __floats2bfloat162_rn(lrelu(c2[0]), lrelu(c2[1]));
            *(__nv_bfloat162*)(t_s + (m0 + r + 8) * APITCH + n)
                = __floats2bfloat162_rn(lrelu(c2[2]), lrelu(c2[3]));
        }
    }
    __syncthreads();

    // ---- P5: dm2 d[128][104] = sigmoid(Wdm2[128][32] @ t), same tiling as P3 ----
    {
        float acc[2][4][4];
        #pragma unroll
        for (int mi = 0; mi < 2; ++mi)
            #pragma unroll
            for (int j = 0; j < 4; ++j)
                acc[mi][j][0] = acc[mi][j][1] = acc[mi][j][2] = acc[mi][j][3] = 0.f;

        const uint4* fA0 = ((const uint4*)g_Wdm2Frag) + (2 * mg) * 2 * 32 + lane;
        const uint4* fA1 = fA0 + 2 * 32;
        unsigned bBase = (unsigned)__cvta_generic_to_shared(t_s)
                         + ((lane & 15) * APITCH + (nt0 + (lane >> 4)) * 8) * 2;
        #pragma unroll
        for (int ks = 0; ks < 2; ++ks) {
            uint4 a0 = fA0[ks * 32];
            uint4 a1 = fA1[ks * 32];
            unsigned bRow = bBase + ks * 16 * APITCH * 2;
            unsigned b0, b1, b2, b3;
            ldmatrix_x4t(b0, b1, b2, b3, bRow);
            mma_bf16(acc[0][0][0], acc[0][0][1], acc[0][0][2], acc[0][0][3],
                     a0.x, a0.y, a0.z, a0.w, b0, b1);
            mma_bf16(acc[1][0][0], acc[1][0][1], acc[1][0][2], acc[1][0][3],
                     a1.x, a1.y, a1.z, a1.w, b0, b1);
            mma_bf16(acc[0][1][0], acc[0][1][1], acc[0][1][2], acc[0][1][3],
                     a0.x, a0.y, a0.z, a0.w, b2, b3);
            mma_bf16(acc[1][1][0], acc[1][1][1], acc[1][1][2], acc[1][1][3],
                     a1.x, a1.y, a1.z, a1.w, b2, b3);
            if (ncnt == 4) {
                ldmatrix_x4t(b0, b1, b2, b3, bRow + 32);
                mma_bf16(acc[0][2][0], acc[0][2][1], acc[0][2][2], acc[0][2][3],
                         a0.x, a0.y, a0.z, a0.w, b0, b1);
                mma_bf16(acc[1][2][0], acc[1][2][1], acc[1][2][2], acc[1][2][3],
                         a1.x, a1.y, a1.z, a1.w, b0, b1);
                mma_bf16(acc[0][3][0], acc[0][3][1], acc[0][3][2], acc[0][3][3],
                         a0.x, a0.y, a0.z, a0.w, b2, b3);
                mma_bf16(acc[1][3][0], acc[1][3][1], acc[1][3][2], acc[1][3][3],
                         a1.x, a1.y, a1.z, a1.w, b2, b3);
            } else {
                ldmatrix_x2t(b0, b1, bRow + 32);
                mma_bf16(acc[0][2][0], acc[0][2][1], acc[0][2][2], acc[0][2][3],
                         a0.x, a0.y, a0.z, a0.w, b0, b1);
                mma_bf16(acc[1][2][0], acc[1][2][1], acc[1][2][2], acc[1][2][3],
                         a1.x, a1.y, a1.z, a1.w, b0, b1);
            }
        }
        #pragma unroll
        for (int mi = 0; mi < 2; ++mi) {
            int o0 = (2 * mg + mi) * 16;
            #pragma unroll
            for (int j = 0; j < 4; ++j) {
                if (j < ncnt) {
                    int n = (nt0 + j) * 8 + cp;
                    float d0 = 1.f / (1.f + __expf(-acc[mi][j][0]));
                    float d1 = 1.f / (1.f + __expf(-acc[mi][j][1]));
                    float d2 = 1.f / (1.f + __expf(-acc[mi][j][2]));
                    float d3 = 1.f / (1.f + __expf(-acc[mi][j][3]));
                    *(__nv_bfloat162*)(d_s + (o0 + r) * APITCH + n)
                        = __floats2bfloat162_rn(d0, d1);
                    *(__nv_bfloat162*)(d_s + (o0 + r + 8) * APITCH + n)
                        = __floats2bfloat162_rn(d2, d3);
                }
            }
        }
    }
    __syncthreads();

    // ---- P6: out = x + scale * epi * d: 6 full rounds + 128-thread tail ----
    const float s = scale_p[0];
    float* ob = out + (long)b * Cdim * HW;
    #pragma unroll
    for (int it = 0; it < 6; ++it) {
        int idx = tid + it * 512;
        int c = idx / 25, rem = idx - c * 25;
        int rr = rem / 5, v = rem - rr * 5;
        long g = (long)c * HW + (long)(R0 + rr) * 320 + C0 + v * 4;
        int pb = c * APITCH + rr * 20 + v * 4;
        float4 xv = *(const float4*)(xb + g);
        __nv_bfloat162 ea = ((const __nv_bfloat162*)(epi_s + pb))[0];
        __nv_bfloat162 eb = ((const __nv_bfloat162*)(epi_s + pb))[1];
        __nv_bfloat162 da = ((const __nv_bfloat162*)(d_s + pb))[0];
        __nv_bfloat162 db = ((const __nv_bfloat162*)(d_s + pb))[1];
        float2 e0 = __bfloat1622float2(ea), e1 = __bfloat1622float2(eb);
        float2 f0 = __bfloat1622float2(da), f1 = __bfloat1622float2(db);
        xv.x += s * e0.x * f0.x;
        xv.y += s * e0.y * f0.y;
        xv.z += s * e1.x * f1.x;
        xv.w += s * e1.y * f1.y;
        *(float4*)(ob + g) = xv;
    }
    if (tid < 128) {
        int idx = tid + 3072;
        int c = idx / 25, rem = idx - c * 25;
        int rr = rem / 5, v = rem - rr * 5;
        long g = (long)c * HW + (long)(R0 + rr) * 320 + C0 + v * 4;
        int pb = c * APITCH + rr * 20 + v * 4;
        float4 xv = *(const float4*)(xb + g);
        __nv_bfloat162 ea = ((const __nv_bfloat162*)(epi_s + pb))[0];
        __nv_bfloat162 eb = ((const __nv_bfloat162*)(epi_s + pb))[1];
        __nv_bfloat162 da = ((const __nv_bfloat162*)(d_s + pb))[0];
        __nv_bfloat162 db = ((const __nv_bfloat162*)(d_s + pb))[1];
        float2 e0 = __bfloat1622float2(ea), e1 = __bfloat1622float2(eb);
        float2 f0 = __bfloat1622float2(da), f1 = __bfloat1622float2(db);
        xv.x += s * e0.x * f0.x;
        xv.y += s * e0.y * f0.y;
        xv.z += s * e1.x * f1.x;
        xv.w += s * e1.y * f1.y;
        *(float4*)(ob + g) = xv;
    }
}

extern "C" void kernel_launch(void* const* d_in, const int* in_sizes, int n_in,
                              void* d_out, int out_size) {
    const float* x       = (const float*)d_in[0];
    const float* w_h_dw  = (const float*)d_in[1];
    const float* w_h_pw  = (const float*)d_in[2];
    const float* w_v_dw  = (const float*)d_in[3];
    const float* w_v_pw  = (const float*)d_in[4];
    const float* w_dm1   = (const float*)d_in[5];
    const float* w_dm2   = (const float*)d_in[6];
    const float* w_fuse  = (const float*)d_in[7];
    const float* scale   = (const float*)d_in[8];

    precompute_pack_kernel<<<130, 256>>>(w_h_pw, w_v_pw, w_dm1, w_dm2, w_fuse);

    cudaFuncSetAttribute(epi_mma_kernel,
                         cudaFuncAttributeMaxDynamicSharedMemorySize, SMEM_BYTES);

    // PDL launch: overlap main kernel's P1/P2 with the prologue.
    cudaLaunchConfig_t cfg = {};
    cfg.gridDim = dim3(320 / 20, 320 / 5, 2);
    cfg.blockDim = dim3(512, 1, 1);
    cfg.dynamicSmemBytes = SMEM_BYTES;
    cfg.stream = 0;
    cudaLaunchAttribute attrs[1];
    attrs[0].id = cudaLaunchAttributeProgrammaticStreamSerialization;
    attrs[0].val.programmaticStreamSerializationAllowed = 1;
    cfg.attrs = attrs;
    cfg.numAttrs = 1;
    cudaLaunchKernelEx(&cfg, epi_mma_kernel,
                       x, w_h_dw, w_v_dw, scale, (float*)d_out);
}

// round 17
// speedup vs baseline: 1.0418x; 1.0418x over previous
#include <cuda_runtime.h>
#include <cuda_bf16.h>

#define Cdim   128
#define HW     102400          // 320*320
#define APITCH 104             // act/epi/t pitch (elems)
#define SXP    108             // sx pitch (f32 words): conflict-free patch reads

// fragment-order A operands: [tile][ks][lane][4 x u32]
__device__ __align__(16) unsigned g_WmainFrag[8 * 16 * 32 * 4];  // 64KB
__device__ __align__(16) unsigned g_Wdm1Frag[2 * 8 * 32 * 4];    // 8KB
__device__ __align__(16) unsigned g_Wdm2Frag[8 * 2 * 32 * 4];    // 2KB

__device__ __forceinline__ unsigned pack_bf2f(float lo, float hi) {
    unsigned u;
    asm("cvt.rn.bf16x2.f32 %0, %1, %2;" : "=r"(u) : "f"(hi), "f"(lo));
    return u;
}

__global__ void precompute_pack_kernel(const float* __restrict__ w_h_pw,
                                       const float* __restrict__ w_v_pw,
                                       const float* __restrict__ w_dm1,
                                       const float* __restrict__ w_dm2,
                                       const float* __restrict__ w_fuse) {
    __shared__ float wf[256];
    int o = blockIdx.x;
    int tid = threadIdx.x;            // 256
    // PDL: let the dependent (main) kernel start its P1/P2 immediately.
    if (tid == 0) cudaTriggerProgrammaticLaunchCompletion();
    if (o < 128) {
        wf[tid] = w_fuse[o * 256 + tid];
        __syncthreads();
        int s = tid >> 7, t = tid & 127;
        const float* mat = s ? w_v_pw : w_h_pw;
        const float* wrow = wf + s * 128;
        float a0 = 0.f, a1 = 0.f, a2 = 0.f, a3 = 0.f;
        #pragma unroll
        for (int j = 0; j < 128; j += 4) {
            a0 += wrow[j    ] * __ldg(mat + (j    ) * 128 + t);
            a1 += wrow[j + 1] * __ldg(mat + (j + 1) * 128 + t);
            a2 += wrow[j + 2] * __ldg(mat + (j + 2) * 128 + t);
            a3 += wrow[j + 3] * __ldg(mat + (j + 3) * 128 + t);
        }
        float acc = (a0 + a1) + (a2 + a3);
        float hi = __shfl_down_sync(0xffffffffu, acc, 1);
        if ((t & 1) == 0) {
            int col = s * 128 + t;
            int rt = o & 15, ot = o >> 4;
            int ks = col >> 4, ct = col & 15;
            int lane_f = (rt & 7) * 4 + ((ct & 7) >> 1);
            int j = (rt >> 3) | ((ct >> 3) << 1);
            g_WmainFrag[((ot * 16 + ks) * 32 + lane_f) * 4 + j] = pack_bf2f(acc, hi);
        }
    } else if (o == 128) {
        for (int idx = tid; idx < 2048; idx += 256) {   // dm1 frags [2][8][32][4]
            int j = idx & 3, lane = (idx >> 2) & 31, ks = (idx >> 7) & 7, mt = idx >> 10;
            int row = mt * 16 + (lane >> 2) + (j & 1) * 8;
            int col = ks * 16 + (lane & 3) * 2 + (j >> 1) * 8;
            g_Wdm1Frag[idx] = pack_bf2f(w_dm1[row * 128 + col], w_dm1[row * 128 + col + 1]);
        }
    } else {
        for (int idx = tid; idx < 512; idx += 256) {    // dm2 frags [8][2][32][4]
            int j = idx & 3, lane = (idx >> 2) & 31, ks = (idx >> 7) & 1, ot = idx >> 8;
            int row = ot * 16 + (lane >> 2) + (j & 1) * 8;
            int col = ks * 16 + (lane & 3) * 2 + (j >> 1) * 8;
            g_Wdm2Frag[idx] = pack_bf2f(w_dm2[row * 32 + col], w_dm2[row * 32 + col + 1]);
        }
    }
}

// ---- mma helpers ----
__device__ __forceinline__ void ldmatrix_x2t(unsigned &r0, unsigned &r1, unsigned addr) {
    asm volatile("ldmatrix.sync.aligned.m8n8.x2.trans.shared.b16 {%0,%1}, [%2];"
                 : "=r"(r0), "=r"(r1) : "r"(addr));
}
__device__ __forceinline__ void ldmatrix_x4t(unsigned &r0, unsigned &r1,
                                             unsigned &r2, unsigned &r3, unsigned addr) {
    asm volatile("ldmatrix.sync.aligned.m8n8.x4.trans.shared.b16 {%0,%1,%2,%3}, [%4];"
                 : "=r"(r0), "=r"(r1), "=r"(r2), "=r"(r3) : "r"(addr));
}
__device__ __forceinline__ void mma_bf16(float &c0, float &c1, float &c2, float &c3,
                                         unsigned a0, unsigned a1, unsigned a2, unsigned a3,
                                         unsigned b0, unsigned b1) {
    asm volatile("mma.sync.aligned.m16n8k16.row.col.f32.bf16.bf16.f32 "
                 "{%0,%1,%2,%3}, {%4,%5,%6,%7}, {%8,%9}, {%0,%1,%2,%3};"
                 : "+f"(c0), "+f"(c1), "+f"(c2), "+f"(c3)
                 : "r"(a0), "r"(a1), "r"(a2), "r"(a3), "r"(b0), "r"(b1));
}

__device__ __forceinline__ void cp16(void* smem_dst, const void* gsrc) {
    unsigned s = (unsigned)__cvta_generic_to_shared(smem_dst);
    asm volatile("cp.async.ca.shared.global [%0], [%1], 16;" :: "r"(s), "l"(gsrc));
}

__device__ __forceinline__ float lrelu(float x) { return fmaxf(x, 0.1f * x); }

__device__ __forceinline__ void conv5(const float w[5],
                                      float x0, float x1, float x2, float x3, float x4,
                                      float o[5]) {
    o[0] = w[2]*x0 + w[3]*x1 + w[4]*x2;
    o[1] = w[1]*x0 + w[2]*x1 + w[3]*x2 + w[4]*x3;
    o[2] = w[0]*x0 + w[1]*x1 + w[2]*x2 + w[3]*x3 + w[4]*x4;
    o[3] = w[0]*x1 + w[1]*x2 + w[2]*x3 + w[3]*x4;
    o[4] = w[0]*x2 + w[1]*x3 + w[2]*x4;
}

__device__ __forceinline__ void store5(__nv_bfloat16* p, int sub,
                                       float a0, float a1, float a2, float a3, float a4) {
    a0 = lrelu(a0); a1 = lrelu(a1); a2 = lrelu(a2); a3 = lrelu(a3); a4 = lrelu(a4);
    if (sub & 1) {
        p[0] = __float2bfloat16(a0);
        *(__nv_bfloat162*)(p + 1) = __floats2bfloat162_rn(a1, a2);
        *(__nv_bfloat162*)(p + 3) = __floats2bfloat162_rn(a3, a4);
    } else {
        *(__nv_bfloat162*)(p)     = __floats2bfloat162_rn(a0, a1);
        *(__nv_bfloat162*)(p + 2) = __floats2bfloat162_rn(a2, a3);
        p[4] = __float2bfloat16(a4);
    }
}

// ---- shared memory layout (bytes) ----
// 0      : act [256][APITCH] bf16  53248   (d_s aliases after P3)
// 53248  : region (55296):
//            sx    f32 [128][SXP]      55296  (P1/P2 only)
//            epi_s [128][APITCH] bf16  26624  (+0)
//            t_s   [32][APITCH]  bf16   6656  (+26624)
// total 108544  -> 2 CTAs/SM
#define SMEM_BYTES 108544

__global__ __launch_bounds__(512, 2)
void epi_mma_kernel(const float* __restrict__ x,
                    const float* __restrict__ w_h_dw,
                    const float* __restrict__ w_v_dw,
                    const float* __restrict__ scale_p,
                    float* __restrict__ out) {
    extern __shared__ char smem[];
    __nv_bfloat16* act   = (__nv_bfloat16*)(smem);
    char* region = smem + 53248;
    float* sx            = (float*)(region);
    __nv_bfloat16* epi_s = (__nv_bfloat16*)(region);
    __nv_bfloat16* t_s   = (__nv_bfloat16*)(region + 26624);
    __nv_bfloat16* d_s = act;   // alias; act dead after P3

    const int tid  = threadIdx.x;
    const int lane = tid & 31;
    const int warp = tid >> 5;
    const int C0 = blockIdx.x * 20;
    const int R0 = blockIdx.y * 5;
    const int b  = blockIdx.z;
    const float* xb = x + (long)b * Cdim * HW;

    // ---- P1: stage x tile via cp.async (no register round-trip) ----
    #pragma unroll
    for (int it = 0; it < 6; ++it) {
        int idx = tid + it * 512;
        int row = idx / 5, q = idx - row * 5;
        int c = row / 5, r = row - c * 5;
        cp16(sx + c * SXP + r * 20 + q * 4,
             xb + (long)c * HW + (R0 + r) * 320 + C0 + q * 4);
    }
    if (tid < 128) {
        int idx = tid + 3072;
        int row = idx / 5, q = idx - row * 5;
        int c = row / 5, r = row - c * 5;
        cp16(sx + c * SXP + r * 20 + q * 4,
             xb + (long)c * HW + (R0 + r) * 320 + C0 + q * 4);
    }
    asm volatile("cp.async.commit_group;" ::: "memory");
    {   // zero act cols 100..103 for all 256 rows
        int k = tid >> 1, q = tid & 1;
        *(__nv_bfloat162*)(act + k * APITCH + 100 + q * 2) = __floats2bfloat162_rn(0.f, 0.f);
    }
    asm volatile("cp.async.wait_group 0;" ::: "memory");
    __syncthreads();

    // ---- P2: depthwise 1x5 / 5x1 on one 5x5 patch + lrelu -> act bf16 [K][N] ----
    {
        const int c = tid >> 2, sub = tid & 3;
        float wh[5], wv[5];
        #pragma unroll
        for (int k = 0; k < 5; ++k) {
            wh[k] = __ldg(w_h_dw + c * 5 + k);
            wv[k] = __ldg(w_v_dw + c * 5 + k);
        }
        const float* sp = sx + c * SXP + sub * 5;
        __nv_bfloat16* ah = act + c * APITCH + sub * 5;
        __nv_bfloat16* av = act + (128 + c) * APITCH + sub * 5;

        float va[5][5];
        #pragma unroll
        for (int ro = 0; ro < 5; ++ro)
            #pragma unroll
            for (int j = 0; j < 5; ++j) va[ro][j] = 0.f;

        #pragma unroll
        for (int rr = 0; rr < 5; ++rr) {
            float xr[5];
            #pragma unroll
            for (int j = 0; j < 5; ++j) xr[j] = sp[rr * 20 + j];
            float o[5];
            conv5(wh, xr[0], xr[1], xr[2], xr[3], xr[4], o);
            store5(ah + rr * 20, sub, o[0], o[1], o[2], o[3], o[4]);
            #pragma unroll
            for (int k = 0; k < 5; ++k) {
                int ro = rr + 2 - k;
                if (ro >= 0 && ro < 5) {
                    float w = wv[k];
                    #pragma unroll
                    for (int j = 0; j < 5; ++j) va[ro][j] += w * xr[j];
                }
            }
        }
        #pragma unroll
        for (int ro = 0; ro < 5; ++ro)
            store5(av + ro * 20, sub, va[ro][0], va[ro][1], va[ro][2], va[ro][3], va[ro][4]);
    }
    // PDL: prologue outputs consumed from here on.
    cudaGridDependencySynchronize();
    __syncthreads();   // act ready; sx dead

    // ---- P3: main GEMM epi[128][104] = Wm[128][256] @ act[256][104] ----
    const int mg   = warp & 3;
    const int ng   = warp >> 2;
    const int nt0  = (ng == 0) ? 0 : 4 + (ng - 1) * 3;
    const int ncnt = (ng == 0) ? 4 : 3;
    const int r  = lane >> 2, cp = (lane & 3) * 2;

    {
        float acc[2][4][4];
        #pragma unroll
        for (int mi = 0; mi < 2; ++mi)
            #pragma unroll
            for (int j = 0; j < 4; ++j)
                acc[mi][j][0] = acc[mi][j][1] = acc[mi][j][2] = acc[mi][j][3] = 0.f;

        const uint4* fA0 = ((const uint4*)g_WmainFrag) + (2 * mg) * 16 * 32 + lane;
        const uint4* fA1 = fA0 + 16 * 32;
        unsigned bBase = (unsigned)__cvta_generic_to_shared(act)
                         + ((lane & 15) * APITCH + (nt0 + (lane >> 4)) * 8) * 2;
        #pragma unroll
        for (int ks = 0; ks < 16; ++ks) {
            uint4 a0 = fA0[ks * 32];
            uint4 a1 = fA1[ks * 32];
            unsigned bRow = bBase + ks * 16 * APITCH * 2;
            unsigned b0, b1, b2, b3;
            ldmatrix_x4t(b0, b1, b2, b3, bRow);               // tiles nt0, nt0+1
            mma_bf16(acc[0][0][0], acc[0][0][1], acc[0][0][2], acc[0][0][3],
                     a0.x, a0.y, a0.z, a0.w, b0, b1);
            mma_bf16(acc[1][0][0], acc[1][0][1], acc[1][0][2], acc[1][0][3],
                     a1.x, a1.y, a1.z, a1.w, b0, b1);
            mma_bf16(acc[0][1][0], acc[0][1][1], acc[0][1][2], acc[0][1][3],
                     a0.x, a0.y, a0.z, a0.w, b2, b3);
            mma_bf16(acc[1][1][0], acc[1][1][1], acc[1][1][2], acc[1][1][3],
                     a1.x, a1.y, a1.z, a1.w, b2, b3);
            if (ncnt == 4) {
                ldmatrix_x4t(b0, b1, b2, b3, bRow + 32);      // tiles nt0+2, nt0+3
                mma_bf16(acc[0][2][0], acc[0][2][1], acc[0][2][2], acc[0][2][3],
                         a0.x, a0.y, a0.z, a0.w, b0, b1);
                mma_bf16(acc[1][2][0], acc[1][2][1], acc[1][2][2], acc[1][2][3],
                         a1.x, a1.y, a1.z, a1.w, b0, b1);
                mma_bf16(acc[0][3][0], acc[0][3][1], acc[0][3][2], acc[0][3][3],
                         a0.x, a0.y, a0.z, a0.w, b2, b3);
                mma_bf16(acc[1][3][0], acc[1][3][1], acc[1][3][2], acc[1][3][3],
                         a1.x, a1.y, a1.z, a1.w, b2, b3);
            } else {
                ldmatrix_x2t(b0, b1, bRow + 32);              // tile nt0+2 (lanes 0-15)
                mma_bf16(acc[0][2][0], acc[0][2][1], acc[0][2][2], acc[0][2][3],
                         a0.x, a0.y, a0.z, a0.w, b0, b1);
                mma_bf16(acc[1][2][0], acc[1][2][1], acc[1][2][2], acc[1][2][3],
                         a1.x, a1.y, a1.z, a1.w, b0, b1);
            }
        }
        #pragma unroll
        for (int mi = 0; mi < 2; ++mi) {
            int o0 = (2 * mg + mi) * 16;
            #pragma unroll
            for (int j = 0; j < 4; ++j) {
                if (j < ncnt) {
                    int n = (nt0 + j) * 8 + cp;
                    *(__nv_bfloat162*)(epi_s + (o0 + r) * APITCH + n)
                        = __floats2bfloat162_rn(acc[mi][j][0], acc[mi][j][1]);
                    *(__nv_bfloat162*)(epi_s + (o0 + r + 8) * APITCH + n)
                        = __floats2bfloat162_rn(acc[mi][j][2], acc[mi][j][3]);
                }
            }
        }
    }
    __syncthreads();   // epi ready (sx region now epi)

    // ---- P4: dm1 t[32][104] = lrelu(Wdm1[32][128] @ epi) ----
    {
        int mt = warp & 1, m0 = mt * 16;
        int nt1 = warp >> 1;
        int nt2 = nt1 + 8;
        bool has2 = (warp < 10);
        float c1[4] = {0.f, 0.f, 0.f, 0.f}, c2[4] = {0.f, 0.f, 0.f, 0.f};
        const uint4* wf1 = ((const uint4*)g_Wdm1Frag) + mt * 8 * 32 + lane;
        unsigned bB = (unsigned)__cvta_generic_to_shared(epi_s)
                      + ((lane & 15) * APITCH) * 2;
        if (has2) {
            unsigned bB4 = bB + ((nt1 + (lane >> 4) * 8) * 8) * 2;
            #pragma unroll
            for (int ks = 0; ks < 8; ++ks) {
                uint4 a = wf1[ks * 32];
                unsigned b0, b1, b2, b3;
                ldmatrix_x4t(b0, b1, b2, b3, bB4 + ks * 16 * APITCH * 2);
                mma_bf16(c1[0], c1[1], c1[2], c1[3], a.x, a.y, a.z, a.w, b0, b1);
                mma_bf16(c2[0], c2[1], c2[2], c2[3], a.x, a.y, a.z, a.w, b2, b3);
            }
        } else {
            #pragma unroll
            for (int ks = 0; ks < 8; ++ks) {
                uint4 a = wf1[ks * 32];
                unsigned b0, b1;
                ldmatrix_x2t(b0, b1, bB + ks * 16 * APITCH * 2 + nt1 * 16);
                mma_bf16(c1[0], c1[1], c1[2], c1[3], a.x, a.y, a.z, a.w, b0, b1);
            }
        }
        {
            int n = nt1 * 8 + cp;
            *(__nv_bfloat162*)(t_s + (m0 + r) * APITCH + n)
                = __floats2bfloat162_rn(lrelu(c1[0]), lrelu(c1[1]));
            *(__nv_bfloat162*)(t_s + (m0 + r + 8) * APITCH + n)
                = __floats2bfloat162_rn(lrelu(c1[2]), lrelu(c1[3]));
        }
        if (has2) {
            int n = nt2 * 8 + cp;
            *(__nv_bfloat162*)(t_s + (m0 + r) * APITCH + n)
                = __floats2bfloat162_rn(lrelu(c2[0]), lrelu(c2[1]));
            *(__nv_bfloat162*)(t_s + (m0 + r + 8) * APITCH + n)
                = __floats2bfloat162_rn(lrelu(c2[2]), lrelu(c2[3]));
        }
    }
    __syncthreads();

    // ---- P5: dm2 d[128][104] = sigmoid(Wdm2[128][32] @ t), same tiling as P3 ----
    {
        float acc[2][4][4];
        #pragma unroll
        for (int mi = 0; mi < 2; ++mi)
            #pragma unroll
            for (int j = 0; j < 4; ++j)
                acc[mi][j][0] = acc[mi][j][1] = acc[mi][j][2] = acc[mi][j][3] = 0.f;

        const uint4* fA0 = ((const uint4*)g_Wdm2Frag) + (2 * mg) * 2 * 32 + lane;
        const uint4* fA1 = fA0 + 2 * 32;
        unsigned bBase = (unsigned)__cvta_generic_to_shared(t_s)
                         + ((lane & 15) * APITCH + (nt0 + (lane >> 4)) * 8) * 2;
        #pragma unroll
        for (int ks = 0; ks < 2; ++ks) {
            uint4 a0 = fA0[ks * 32];
            uint4 a1 = fA1[ks * 32];
            unsigned bRow = bBase + ks * 16 * APITCH * 2;
            unsigned b0, b1, b2, b3;
            ldmatrix_x4t(b0, b1, b2, b3, bRow);
            mma_bf16(acc[0][0][0], acc[0][0][1], acc[0][0][2], acc[0][0][3],
                     a0.x, a0.y, a0.z, a0.w, b0, b1);
            mma_bf16(acc[1][0][0], acc[1][0][1], acc[1][0][2], acc[1][0][3],
                     a1.x, a1.y, a1.z, a1.w, b0, b1);
            mma_bf16(acc[0][1][0], acc[0][1][1], acc[0][1][2], acc[0][1][3],
                     a0.x, a0.y, a0.z, a0.w, b2, b3);
            mma_bf16(acc[1][1][0], acc[1][1][1], acc[1][1][2], acc[1][1][3],
                     a1.x, a1.y, a1.z, a1.w, b2, b3);
            if (ncnt == 4) {
                ldmatrix_x4t(b0, b1, b2, b3, bRow + 32);
                mma_bf16(acc[0][2][0], acc[0][2][1], acc[0][2][2], acc[0][2][3],
                         a0.x, a0.y, a0.z, a0.w, b0, b1);
                mma_bf16(acc[1][2][0], acc[1][2][1], acc[1][2][2], acc[1][2][3],
                         a1.x, a1.y, a1.z, a1.w, b0, b1);
                mma_bf16(acc[0][3][0], acc[0][3][1], acc[0][3][2], acc[0][3][3],
                         a0.x, a0.y, a0.z, a0.w, b2, b3);
                mma_bf16(acc[1][3][0], acc[1][3][1], acc[1][3][2], acc[1][3][3],
                         a1.x, a1.y, a1.z, a1.w, b2, b3);
            } else {
                ldmatrix_x2t(b0, b1, bRow + 32);
                mma_bf16(acc[0][2][0], acc[0][2][1], acc[0][2][2], acc[0][2][3],
                         a0.x, a0.y, a0.z, a0.w, b0, b1);
                mma_bf16(acc[1][2][0], acc[1][2][1], acc[1][2][2], acc[1][2][3],
                         a1.x, a1.y, a1.z, a1.w, b0, b1);
            }
        }
        #pragma unroll
        for (int mi = 0; mi < 2; ++mi) {
            int o0 = (2 * mg + mi) * 16;
            #pragma unroll
            for (int j = 0; j < 4; ++j) {
                if (j < ncnt) {
                    int n = (nt0 + j) * 8 + cp;
                    float d0 = 1.f / (1.f + __expf(-acc[mi][j][0]));
                    float d1 = 1.f / (1.f + __expf(-acc[mi][j][1]));
                    float d2 = 1.f / (1.f + __expf(-acc[mi][j][2]));
                    float d3 = 1.f / (1.f + __expf(-acc[mi][j][3]));
                    *(__nv_bfloat162*)(d_s + (o0 + r) * APITCH + n)
                        = __floats2bfloat162_rn(d0, d1);
                    *(__nv_bfloat162*)(d_s + (o0 + r + 8) * APITCH + n)
                        = __floats2bfloat162_rn(d2, d3);
                }
            }
        }
    }
    __syncthreads();

    // ---- P6: out = x + scale * epi * d: 6 full rounds + 128-thread tail ----
    const float s = scale_p[0];
    float* ob = out + (long)b * Cdim * HW;
    #pragma unroll
    for (int it = 0; it < 6; ++it) {
        int idx = tid + it * 512;
        int c = idx / 25, rem = idx - c * 25;
        int rr = rem / 5, v = rem - rr * 5;
        long g = (long)c * HW + (long)(R0 + rr) * 320 + C0 + v * 4;
        int pb = c * APITCH + rr * 20 + v * 4;
        float4 xv = *(const float4*)(xb + g);
        __nv_bfloat162 ea = ((const __nv_bfloat162*)(epi_s + pb))[0];
        __nv_bfloat162 eb = ((const __nv_bfloat162*)(epi_s + pb))[1];
        __nv_bfloat162 da = ((const __nv_bfloat162*)(d_s + pb))[0];
        __nv_bfloat162 db = ((const __nv_bfloat162*)(d_s + pb))[1];
        float2 e0 = __bfloat1622float2(ea), e1 = __bfloat1622float2(eb);
        float2 f0 = __bfloat1622float2(da), f1 = __bfloat1622float2(db);
        xv.x += s * e0.x * f0.x;
        xv.y += s * e0.y * f0.y;
        xv.z += s * e1.x * f1.x;
        xv.w += s * e1.y * f1.y;
        *(float4*)(ob + g) = xv;
    }
    if (tid < 128) {
        int idx = tid + 3072;
        int c = idx / 25, rem = idx - c * 25;
        int rr = rem / 5, v = rem - rr * 5;
        long g = (long)c * HW + (long)(R0 + rr) * 320 + C0 + v * 4;
        int pb = c * APITCH + rr * 20 + v * 4;
        float4 xv = *(const float4*)(xb + g);
        __nv_bfloat162 ea = ((const __nv_bfloat162*)(epi_s + pb))[0];
        __nv_bfloat162 eb = ((const __nv_bfloat162*)(epi_s + pb))[1];
        __nv_bfloat162 da = ((const __nv_bfloat162*)(d_s + pb))[0];
        __nv_bfloat162 db = ((const __nv_bfloat162*)(d_s + pb))[1];
        float2 e0 = __bfloat1622float2(ea), e1 = __bfloat1622float2(eb);
        float2 f0 = __bfloat1622float2(da), f1 = __bfloat1622float2(db);
        xv.x += s * e0.x * f0.x;
        xv.y += s * e0.y * f0.y;
        xv.z += s * e1.x * f1.x;
        xv.w += s * e1.y * f1.y;
        *(float4*)(ob + g) = xv;
    }
}

extern "C" void kernel_launch(void* const* d_in, const int* in_sizes, int n_in,
                              void* d_out, int out_size) {
    const float* x       = (const float*)d_in[0];
    const float* w_h_dw  = (const float*)d_in[1];
    const float* w_h_pw  = (const float*)d_in[2];
    const float* w_v_dw  = (const float*)d_in[3];
    const float* w_v_pw  = (const float*)d_in[4];
    const float* w_dm1   = (const float*)d_in[5];
    const float* w_dm2   = (const float*)d_in[6];
    const float* w_fuse  = (const float*)d_in[7];
    const float* scale   = (const float*)d_in[8];

    precompute_pack_kernel<<<130, 256>>>(w_h_pw, w_v_pw, w_dm1, w_dm2, w_fuse);

    cudaFuncSetAttribute(epi_mma_kernel,
                         cudaFuncAttributeMaxDynamicSharedMemorySize, SMEM_BYTES);

    // PDL launch: overlap main kernel's P1/P2 with the prologue.
    cudaLaunchConfig_t cfg = {};
    cfg.gridDim = dim3(320 / 20, 320 / 5, 2);
    cfg.blockDim = dim3(512, 1, 1);
    cfg.dynamicSmemBytes = SMEM_BYTES;
    cfg.stream = 0;
    cudaLaunchAttribute attrs[1];
    attrs[0].id = cudaLaunchAttributeProgrammaticStreamSerialization;
    attrs[0].val.programmaticStreamSerializationAllowed = 1;
    cfg.attrs = attrs;
    cfg.numAttrs = 1;
    cudaLaunchKernelEx(&cfg, epi_mma_kernel,
                       x, w_h_dw, w_v_dw, scale, (float*)d_out);
}